// round 15
// baseline (speedup 1.0000x reference)
#include <cuda_runtime.h>
#include <cuda_fp16.h>
#include <math.h>
#include <stdint.h>

// ---------------------------------------------------------------------------
// Problem constants
// ---------------------------------------------------------------------------
#define BATCH 2
#define SEQT  2048
#define EMB   1024
#define NHEAD 16
#define HDIM  64
#define E3    3072
#define MROWS (BATCH*SEQT)   // 4096
#define KDIM  1024

#define NSM   148

// ---------------------------------------------------------------------------
// Scratch (__device__ globals; no runtime allocation)
// ---------------------------------------------------------------------------
__device__ __half g_x16[(size_t)MROWS * KDIM];               // x fp16
__device__ __half g_w1[(size_t)E3 * KDIM];                   // W1 fp16
__device__ __half g_w2[(size_t)EMB * KDIM];                  // W2 fp16
__device__ __half g_ah[(size_t)MROWS * KDIM];                // attn out
__device__ __half g_qh[(size_t)BATCH * NHEAD * SEQT * HDIM]; // q (scaled, rope)
__device__ __half g_kh[(size_t)BATCH * NHEAD * SEQT * HDIM]; // k (rope)
__device__ __half g_vh[(size_t)BATCH * NHEAD * SEQT * HDIM]; // v

#define QSCALE 0.18033688011112042f   // 0.125 * log2(e)
#define LOG2_10000_OVER32 (13.287712379549449f / 32.0f)

// ---------------------------------------------------------------------------
// Helpers
// ---------------------------------------------------------------------------
__device__ __forceinline__ uint32_t smem_u32(const void* p) {
    uint32_t a;
    asm("{ .reg .u64 t; cvta.to.shared.u64 t, %1; cvt.u32.u64 %0, t; }" : "=r"(a) : "l"(p));
    return a;
}
__device__ __forceinline__ void cp_async16(uint32_t dst, const void* src) {
    asm volatile("cp.async.cg.shared.global [%0], [%1], 16;" :: "r"(dst), "l"(src));
}
__device__ __forceinline__ void cp_commit() {
    asm volatile("cp.async.commit_group;" ::: "memory");
}
template <int N> __device__ __forceinline__ void cp_wait() {
    asm volatile("cp.async.wait_group %0;" :: "n"(N) : "memory");
}
__device__ __forceinline__ void ldsm4(uint32_t* r, uint32_t addr) {
    asm volatile("ldmatrix.sync.aligned.m8n8.x4.shared.b16 {%0,%1,%2,%3}, [%4];"
        : "=r"(r[0]), "=r"(r[1]), "=r"(r[2]), "=r"(r[3]) : "r"(addr));
}
__device__ __forceinline__ void ldsm4t(uint32_t* r, uint32_t addr) {
    asm volatile("ldmatrix.sync.aligned.m8n8.x4.trans.shared.b16 {%0,%1,%2,%3}, [%4];"
        : "=r"(r[0]), "=r"(r[1]), "=r"(r[2]), "=r"(r[3]) : "r"(addr));
}
__device__ __forceinline__ void mma_f16(float* c, const uint32_t* a, uint32_t b0, uint32_t b1) {
    asm volatile(
        "mma.sync.aligned.m16n8k16.row.col.f32.f16.f16.f32 "
        "{%0,%1,%2,%3}, {%4,%5,%6,%7}, {%8,%9}, {%0,%1,%2,%3};"
        : "+f"(c[0]), "+f"(c[1]), "+f"(c[2]), "+f"(c[3])
        : "r"(a[0]), "r"(a[1]), "r"(a[2]), "r"(a[3]), "r"(b0), "r"(b1));
}

// ---------------------------------------------------------------------------
// Merged conversion: x, W1, W2 -> fp16 in ONE launch (range dispatch).
// ---------------------------------------------------------------------------
#define XN4  (MROWS * KDIM / 4)          // 1048576
#define W1N4 (E3 * KDIM / 4)             // 786432
#define W2N4 (EMB * KDIM / 4)            // 262144
#define ALLN4 (XN4 + W1N4 + W2N4)        // 2097152

__global__ void convert_all(const float* __restrict__ x, const float* __restrict__ W1,
                            const float* __restrict__ W2,
                            __half* __restrict__ x16, __half* __restrict__ w1,
                            __half* __restrict__ w2)
{
    int i = blockIdx.x * blockDim.x + threadIdx.x;
    const float* src;
    __half* dst;
    int j;
    if (i < XN4) {
        src = x; dst = x16; j = i;
    } else if (i < XN4 + W1N4) {
        src = W1; dst = w1; j = i - XN4;
    } else if (i < ALLN4) {
        src = W2; dst = w2; j = i - XN4 - W1N4;
    } else {
        return;
    }
    float4 v = ((const float4*)src)[j];
    __half2* dp = (__half2*)dst;
    dp[2 * j]     = __floats2half2_rn(v.x, v.y);
    dp[2 * j + 1] = __floats2half2_rn(v.z, v.w);
}

// ---------------------------------------------------------------------------
// fp16 mma GEMM, persistent tiles. C[M,N] = A[M,K] @ B[N,K]^T.
// MODE 0: fp32 C out.  MODE 2: fused RoPE+repack epilogue to qh/kh/vh.
// Block tile 128x256x64, ONE CTA of 256 threads (8 warps as 2m x 4n),
// warp tile 64x64 (4 m16 x 4 n16), 3-stage cp.async ring, 1 CTA/SM.
// ---------------------------------------------------------------------------
#define GBM 128
#define GBN 256
#define GBK 64
#define GSK 72                          // padded smem stride (halves)
#define AMAT (GBM * GSK)                // 9216 halves  (18432 B)
#define BMAT (GBN * GSK)                // 18432 halves (36864 B)
#define GSTAGE ((AMAT + BMAT) * 2)      // 55296 bytes per stage
#define GEMM_SMEM (3 * GSTAGE)          // 165888 bytes
#define NCH (KDIM / GBK)                // 16

__device__ __forceinline__ void g2_load(
    uint32_t s0, int tid, int kc, int m0, int n0,
    const __half* __restrict__ A, const __half* __restrict__ B)
{
    const __half* a0 = A + (size_t)m0 * KDIM + kc * GBK;
    const __half* b0 = B + (size_t)n0 * KDIM + kc * GBK;
    // A: 128 rows x 8 chunks(16B) = 1024 chunks; 4 per thread
    #pragma unroll
    for (int it = 0; it < 4; it++) {
        const int jj = tid + it * 256;
        const int row = jj >> 3;
        const int c = jj & 7;
        cp_async16(s0 + (uint32_t)(row * GSK + c * 8) * 2,
                   a0 + (size_t)row * KDIM + c * 8);
    }
    // B: 256 rows x 8 chunks = 2048 chunks; 8 per thread
    const uint32_t sB0 = s0 + AMAT * 2;
    #pragma unroll
    for (int it = 0; it < 8; it++) {
        const int jj = tid + it * 256;
        const int row = jj >> 3;
        const int c = jj & 7;
        cp_async16(sB0 + (uint32_t)(row * GSK + c * 8) * 2,
                   b0 + (size_t)row * KDIM + c * 8);
    }
    cp_commit();
}

template <int MODE>
__global__ void __launch_bounds__(256, 1)
gemm_f16(const __half* __restrict__ A, const __half* __restrict__ B,
         float* __restrict__ C, int N, int numTiles,
         __half* __restrict__ qh, __half* __restrict__ kh, __half* __restrict__ vh)
{
    extern __shared__ char smem[];
    const uint32_t sb = smem_u32(smem);
    const int tid = threadIdx.x;
    const int wid = tid >> 5;
    const int lane = tid & 31;
    const int wm = wid >> 2;    // 0..1  (64 rows each)
    const int wn = wid & 3;     // 0..3  (64 cols each)
    const int ntiles_n = N / GBN;

    float invf[8];
    if (MODE == 2) {
        #pragma unroll
        for (int p = 0; p < 4; p++) {
            const int j0 = p * 8 + 2 * (lane & 3);
            invf[2 * p]     = exp2f(-(float)j0 * LOG2_10000_OVER32);
            invf[2 * p + 1] = exp2f(-(float)(j0 + 1) * LOG2_10000_OVER32);
        }
    }

    for (int t = blockIdx.x; t < numTiles; t += gridDim.x) {
        const int m0 = (t / ntiles_n) * GBM;
        const int n0 = (t % ntiles_n) * GBN;

        float acc[4][8][4];
        #pragma unroll
        for (int i = 0; i < 4; i++)
            #pragma unroll
            for (int j = 0; j < 8; j++)
                #pragma unroll
                for (int k = 0; k < 4; k++) acc[i][j][k] = 0.f;

        g2_load(sb,          tid, 0, m0, n0, A, B);
        g2_load(sb + GSTAGE, tid, 1, m0, n0, A, B);

        for (int c = 0; c < NCH; c++) {
            if (c + 1 < NCH) cp_wait<1>(); else cp_wait<0>();
            __syncthreads();

            const uint32_t scur = sb + (uint32_t)(c % 3) * GSTAGE;
            const uint32_t sA = scur;
            const uint32_t sB = scur + AMAT * 2;

            #pragma unroll
            for (int ks = 0; ks < 4; ks++) {
                const int k0 = ks * 16;
                uint32_t aF[4][4], bk[4][4];
                #pragma unroll
                for (int mi = 0; mi < 4; mi++) {
                    const int row = wm * 64 + mi * 16 + (lane & 15);
                    const int col = k0 + ((lane >> 4) << 3);
                    ldsm4(aF[mi], sA + (uint32_t)(row * GSK + col) * 2);
                }
                #pragma unroll
                for (int p = 0; p < 4; p++) {
                    const int row = wn * 64 + p * 16 + (lane & 7) + ((lane >> 4) << 3);
                    const int col = k0 + (((lane >> 3) & 1) << 3);
                    ldsm4(bk[p], sB + (uint32_t)(row * GSK + col) * 2);
                }
                // 32 MMAs per ks-step
                #pragma unroll
                for (int p = 0; p < 4; p++) {
                    #pragma unroll
                    for (int mi = 0; mi < 4; mi++) {
                        mma_f16(acc[mi][2 * p],     aF[mi], bk[p][0], bk[p][1]);
                        mma_f16(acc[mi][2 * p + 1], aF[mi], bk[p][2], bk[p][3]);
                    }
                }
            }
            if (c + 2 < NCH)
                g2_load(sb + (uint32_t)((c + 2) % 3) * GSTAGE, tid, c + 2, m0, n0, A, B);
        }

        if (MODE == 0) {
            #pragma unroll
            for (int mi = 0; mi < 4; mi++) {
                const int r0 = m0 + wm * 64 + mi * 16 + (lane >> 2);
                #pragma unroll
                for (int nj = 0; nj < 8; nj++) {
                    const int col = n0 + wn * 64 + nj * 8 + 2 * (lane & 3);
                    *(float2*)&C[(size_t)r0 * N + col] =
                        make_float2(acc[mi][nj][0], acc[mi][nj][1]);
                    *(float2*)&C[(size_t)(r0 + 8) * N + col] =
                        make_float2(acc[mi][nj][2], acc[mi][nj][3]);
                }
            }
        } else {
            // fused RoPE + repack epilogue (warp owns one 64-col head of q/k/v)
            const int cbase = n0 + wn * 64;
            const int sec = cbase >> 10;            // 0=q 1=k 2=v
            const int hd  = (cbase & 1023) >> 6;
            __half* dst = (sec == 0) ? qh : (sec == 1) ? kh : vh;

            #pragma unroll
            for (int mi = 0; mi < 4; mi++) {
                #pragma unroll
                for (int rr = 0; rr < 2; rr++) {
                    const int r = m0 + wm * 64 + mi * 16 + (lane >> 2) + rr * 8;
                    const int bb = r >> 11;
                    const int tt = r & 2047;
                    __half* drow = dst + ((size_t)((bb * NHEAD + hd) * SEQT + tt)) * HDIM;
                    if (sec == 2) {
                        #pragma unroll
                        for (int nj = 0; nj < 8; nj++) {
                            const int j0 = nj * 8 + 2 * (lane & 3);
                            *(__half2*)&drow[j0] =
                                __floats2half2_rn(acc[mi][nj][2 * rr], acc[mi][nj][2 * rr + 1]);
                        }
                    } else {
                        const float qs = (sec == 0) ? QSCALE : 1.0f;
                        const float tf = (float)tt;
                        #pragma unroll
                        for (int p = 0; p < 4; p++) {
                            const int j0 = p * 8 + 2 * (lane & 3);
                            const float a0 = acc[mi][p][2 * rr];
                            const float a1 = acc[mi][p][2 * rr + 1];
                            const float b0 = acc[mi][p + 4][2 * rr];
                            const float b1 = acc[mi][p + 4][2 * rr + 1];
                            float s0, c0, s1, c1;
                            sincosf(tf * invf[2 * p], &s0, &c0);
                            sincosf(tf * invf[2 * p + 1], &s1, &c1);
                            *(__half2*)&drow[j0] =
                                __floats2half2_rn(qs * (a0 * c0 - b0 * s0),
                                                  qs * (a1 * c1 - b1 * s1));
                            *(__half2*)&drow[j0 + 32] =
                                __floats2half2_rn(qs * (b0 * c0 + a0 * s0),
                                                  qs * (b1 * c1 + a1 * s1));
                        }
                    }
                }
            }
        }
        __syncthreads();
    }
}

// ---------------------------------------------------------------------------
// fp16 mma causal flash attention. 256 threads (8 warps), 128 queries per
// block. K-tile = 64, double-buffered cp.async. exp2-domain softmax.
// Fully-masked warp tiles skip compute. Dynamic smem 55296 B.
// ---------------------------------------------------------------------------
#define SV 72   // smem row stride (halves)
#define AQT 128
#define ATTN_SQ_OFF 0
#define ATTN_SK_OFF (AQT * SV * 2)                    // 18432
#define ATTN_SV_OFF (ATTN_SK_OFF + 2 * 64 * SV * 2)   // 36864
#define ATTN_SMEM   (ATTN_SV_OFF + 2 * 64 * SV * 2)   // 55296

__global__ void __launch_bounds__(256, 2) attn_mma(
    const __half* __restrict__ qh, const __half* __restrict__ kh,
    const __half* __restrict__ vh, __half* __restrict__ outh)
{
    extern __shared__ char asmem[];
    const uint32_t sbase = smem_u32(asmem);
    const uint32_t sQ = sbase + ATTN_SQ_OFF;
    const uint32_t sKb[2] = { sbase + ATTN_SK_OFF, sbase + ATTN_SK_OFF + 64 * SV * 2 };
    const uint32_t sVb[2] = { sbase + ATTN_SV_OFF, sbase + ATTN_SV_OFF + 64 * SV * 2 };

    const int bh = blockIdx.y;
    const int b = bh >> 4;
    const int h = bh & 15;
    const int qt = (gridDim.x - 1) - blockIdx.x;   // heavy tiles first
    const int tid = threadIdx.x;
    const int wid = tid >> 5;
    const int lane = tid & 31;

    const __half* qg = qh + (size_t)bh * SEQT * HDIM;
    const __half* kg = kh + (size_t)bh * SEQT * HDIM;
    const __half* vg = vh + (size_t)bh * SEQT * HDIM;

    #pragma unroll
    for (int i = 0; i < 4; i++) {
        const int ch = tid + i * 256;
        const int row = ch >> 3;
        const int c = ch & 7;
        cp_async16(sQ + (uint32_t)(row * SV + c * 8) * 2,
                   qg + (size_t)(qt * AQT + row) * HDIM + c * 8);
    }
    cp_commit();

    {
        #pragma unroll
        for (int i = 0; i < 2; i++) {
            const int ch = tid + i * 256;
            const int row = ch >> 3;
            const int c = ch & 7;
            const uint32_t d = (uint32_t)(row * SV + c * 8) * 2;
            const size_t goff = (size_t)row * HDIM + c * 8;
            cp_async16(sKb[0] + d, kg + goff);
            cp_async16(sVb[0] + d, vg + goff);
        }
        cp_commit();
    }

    cp_wait<1>();
    __syncthreads();

    uint32_t aq[4][4];
    #pragma unroll
    for (int ks = 0; ks < 4; ks++) {
        const int row = wid * 16 + (lane & 15);
        const int col = ks * 16 + ((lane >> 4) << 3);
        ldsm4(aq[ks], sQ + (uint32_t)(row * SV + col) * 2);
    }

    float o[8][4];
    #pragma unroll
    for (int j = 0; j < 8; j++)
        #pragma unroll
        for (int k = 0; k < 4; k++) o[j][k] = 0.f;
    float mr[2] = {-1e30f, -1e30f};
    float lr[2] = {0.f, 0.f};

    const int q0g = qt * AQT + wid * 16;
    const int NKT = 2 * qt + 2;

    for (int kt = 0; kt < NKT; kt++) {
        const int cb = kt & 1;
        if (kt + 1 < NKT) {
            const uint32_t sKn = sKb[1 - cb];
            const uint32_t sVn = sVb[1 - cb];
            #pragma unroll
            for (int i = 0; i < 2; i++) {
                const int ch = tid + i * 256;
                const int row = ch >> 3;
                const int c = ch & 7;
                const uint32_t d = (uint32_t)(row * SV + c * 8) * 2;
                const size_t goff = (size_t)((kt + 1) * 64 + row) * HDIM + c * 8;
                cp_async16(sKn + d, kg + goff);
                cp_async16(sVn + d, vg + goff);
            }
            cp_commit();
            cp_wait<1>();
        } else {
            cp_wait<0>();
        }
        __syncthreads();

        const int kbase = kt * 64;
        const bool active = (kbase <= q0g + 15);
        if (active) {
            const uint32_t sK = sKb[cb];
            const uint32_t sV = sVb[cb];

            float sacc[8][4];
            #pragma unroll
            for (int j = 0; j < 8; j++)
                #pragma unroll
                for (int k = 0; k < 4; k++) sacc[j][k] = 0.f;

            #pragma unroll
            for (int ks = 0; ks < 4; ks++) {
                uint32_t bk[4][4];
                #pragma unroll
                for (int p = 0; p < 4; p++) {
                    const int row = p * 16 + (lane & 7) + ((lane >> 4) << 3);
                    const int col = ks * 16 + (((lane >> 3) & 1) << 3);
                    ldsm4(bk[p], sK + (uint32_t)(row * SV + col) * 2);
                }
                #pragma unroll
                for (int p = 0; p < 4; p++) {
                    mma_f16(sacc[2 * p],     aq[ks], bk[p][0], bk[p][1]);
                    mma_f16(sacc[2 * p + 1], aq[ks], bk[p][2], bk[p][3]);
                }
            }

            if (kbase + 63 > q0g) {
                const int qg0 = q0g + (lane >> 2);
                #pragma unroll
                for (int nj = 0; nj < 8; nj++) {
                    const int col = kbase + nj * 8 + 2 * (lane & 3);
                    if (col > qg0)         sacc[nj][0] = -1e30f;
                    if (col + 1 > qg0)     sacc[nj][1] = -1e30f;
                    if (col > qg0 + 8)     sacc[nj][2] = -1e30f;
                    if (col + 1 > qg0 + 8) sacc[nj][3] = -1e30f;
                }
            }

            #pragma unroll
            for (int r = 0; r < 2; r++) {
                float mt = -1e30f;
                #pragma unroll
                for (int nj = 0; nj < 8; nj++)
                    mt = fmaxf(mt, fmaxf(sacc[nj][2 * r], sacc[nj][2 * r + 1]));
                mt = fmaxf(mt, __shfl_xor_sync(0xFFFFFFFFu, mt, 1));
                mt = fmaxf(mt, __shfl_xor_sync(0xFFFFFFFFu, mt, 2));
                const float mnew = fmaxf(mr[r], mt);
                const float alpha = exp2f(mr[r] - mnew);
                mr[r] = mnew;
                lr[r] *= alpha;
                #pragma unroll
                for (int nj = 0; nj < 8; nj++) {
                    o[nj][2 * r] *= alpha;
                    o[nj][2 * r + 1] *= alpha;
                }
                float psum = 0.f;
                #pragma unroll
                for (int nj = 0; nj < 8; nj++) {
                    const float p0 = exp2f(sacc[nj][2 * r] - mnew);
                    const float p1 = exp2f(sacc[nj][2 * r + 1] - mnew);
                    sacc[nj][2 * r] = p0;
                    sacc[nj][2 * r + 1] = p1;
                    psum += p0 + p1;
                }
                lr[r] += psum;
            }

            uint32_t ap[4][4];
            #pragma unroll
            for (int kp = 0; kp < 4; kp++) {
                const int nj = 2 * kp;
                __half2 t0 = __float22half2_rn(make_float2(sacc[nj][0], sacc[nj][1]));
                __half2 t1 = __float22half2_rn(make_float2(sacc[nj][2], sacc[nj][3]));
                __half2 t2 = __float22half2_rn(make_float2(sacc[nj + 1][0], sacc[nj + 1][1]));
                __half2 t3 = __float22half2_rn(make_float2(sacc[nj + 1][2], sacc[nj + 1][3]));
                ap[kp][0] = *(uint32_t*)&t0;
                ap[kp][1] = *(uint32_t*)&t1;
                ap[kp][2] = *(uint32_t*)&t2;
                ap[kp][3] = *(uint32_t*)&t3;
            }

            #pragma unroll
            for (int kp = 0; kp < 4; kp++) {
                uint32_t bv[4][4];
                #pragma unroll
                for (int pd = 0; pd < 4; pd++) {
                    const int row = kp * 16 + (lane & 7) + ((lane >> 4) << 3);
                    const int col = pd * 16 + (((lane >> 3) & 1) << 3);
                    ldsm4t(bv[pd], sV + (uint32_t)(row * SV + col) * 2);
                }
                #pragma unroll
                for (int pd = 0; pd < 4; pd++) {
                    mma_f16(o[2 * pd],     ap[kp], bv[pd][0], bv[pd][2]);
                    mma_f16(o[2 * pd + 1], ap[kp], bv[pd][1], bv[pd][3]);
                }
            }
        }
        __syncthreads();
    }

    float inv[2];
    #pragma unroll
    for (int r = 0; r < 2; r++) {
        float ls = lr[r];
        ls += __shfl_xor_sync(0xFFFFFFFFu, ls, 1);
        ls += __shfl_xor_sync(0xFFFFFFFFu, ls, 2);
        inv[r] = 1.0f / ls;
    }
    #pragma unroll
    for (int r = 0; r < 2; r++) {
        const int trow = qt * AQT + wid * 16 + (lane >> 2) + 8 * r;
        const size_t rowoff = (size_t)(b * SEQT + trow) * EMB + h * HDIM;
        #pragma unroll
        for (int nj = 0; nj < 8; nj++) {
            const int col = nj * 8 + 2 * (lane & 3);
            *(__half2*)&outh[rowoff + col] =
                __floats2half2_rn(o[nj][2 * r] * inv[r], o[nj][2 * r + 1] * inv[r]);
        }
    }
}

// ---------------------------------------------------------------------------
// Launch sequence
// ---------------------------------------------------------------------------
extern "C" void kernel_launch(void* const* d_in, const int* in_sizes, int n_in,
                              void* d_out, int out_size)
{
    const float* x  = (const float*)d_in[0];
    const float* W1 = (const float*)d_in[1];
    const float* W2 = (const float*)d_in[2];
    float* out = (float*)d_out;

    void *p_x16, *p_w1, *p_w2, *p_ah, *p_qh, *p_kh, *p_vh;
    cudaGetSymbolAddress(&p_x16, g_x16);
    cudaGetSymbolAddress(&p_w1, g_w1); cudaGetSymbolAddress(&p_w2, g_w2);
    cudaGetSymbolAddress(&p_ah, g_ah);
    cudaGetSymbolAddress(&p_qh, g_qh); cudaGetSymbolAddress(&p_kh, g_kh);
    cudaGetSymbolAddress(&p_vh, g_vh);

    cudaFuncSetAttribute(gemm_f16<0>, cudaFuncAttributeMaxDynamicSharedMemorySize, GEMM_SMEM);
    cudaFuncSetAttribute(gemm_f16<2>, cudaFuncAttributeMaxDynamicSharedMemorySize, GEMM_SMEM);
    cudaFuncSetAttribute(attn_mma,    cudaFuncAttributeMaxDynamicSharedMemorySize, ATTN_SMEM);

    // one merged conversion launch
    convert_all<<<(ALLN4 + 255) / 256, 256>>>(
        x, W1, W2, (__half*)p_x16, (__half*)p_w1, (__half*)p_w2);

    // qkv = x @ W1^T with fused RoPE + repack epilogue (persistent tiles)
    {
        const int tiles = (MROWS / GBM) * (E3 / GBN);   // 32 * 12 = 384
        const int grid = tiles < NSM ? tiles : NSM;
        gemm_f16<2><<<grid, 256, GEMM_SMEM>>>(
            (const __half*)p_x16, (const __half*)p_w1, nullptr, E3, tiles,
            (__half*)p_qh, (__half*)p_kh, (__half*)p_vh);
    }

    // attention -> fp16
    {
        dim3 ga(SEQT / AQT, BATCH * NHEAD);
        attn_mma<<<ga, 256, ATTN_SMEM>>>((const __half*)p_qh, (const __half*)p_kh,
                                         (const __half*)p_vh, (__half*)p_ah);
    }

    // out = att @ W2^T  (fp32 out, persistent tiles)
    {
        const int tiles = (MROWS / GBM) * (EMB / GBN);  // 32 * 4 = 128
        const int grid = tiles < NSM ? tiles : NSM;
        gemm_f16<0><<<grid, 256, GEMM_SMEM>>>(
            (const __half*)p_ah, (const __half*)p_w2, out, EMB, tiles,
            nullptr, nullptr, nullptr);
    }
}

// round 17
// speedup vs baseline: 1.0492x; 1.0492x over previous
#include <cuda_runtime.h>
#include <cuda_fp16.h>
#include <math.h>
#include <stdint.h>

// ---------------------------------------------------------------------------
// Problem constants
// ---------------------------------------------------------------------------
#define BATCH 2
#define SEQT  2048
#define EMB   1024
#define NHEAD 16
#define HDIM  64
#define E3    3072
#define MROWS (BATCH*SEQT)   // 4096
#define KDIM  1024

#define NSM   148
#define PGRID (2 * NSM)      // persistent grid (2 CTAs/SM)

// ---------------------------------------------------------------------------
// Scratch (__device__ globals; no runtime allocation)
// ---------------------------------------------------------------------------
__device__ __half g_x16[(size_t)MROWS * KDIM];               // x fp16
__device__ __half g_w1[(size_t)E3 * KDIM];                   // W1 fp16
__device__ __half g_w2[(size_t)EMB * KDIM];                  // W2 fp16
__device__ __half g_ah[(size_t)MROWS * KDIM];                // attn out
__device__ __half g_qh[(size_t)BATCH * NHEAD * SEQT * HDIM]; // q (scaled, rope)
__device__ __half g_kh[(size_t)BATCH * NHEAD * SEQT * HDIM]; // k (rope)
__device__ __half g_vh[(size_t)BATCH * NHEAD * SEQT * HDIM]; // v

#define QSCALE 0.18033688011112042f   // 0.125 * log2(e)
#define LOG2_10000_OVER32 (13.287712379549449f / 32.0f)

// ---------------------------------------------------------------------------
// Helpers
// ---------------------------------------------------------------------------
__device__ __forceinline__ uint32_t smem_u32(const void* p) {
    uint32_t a;
    asm("{ .reg .u64 t; cvta.to.shared.u64 t, %1; cvt.u32.u64 %0, t; }" : "=r"(a) : "l"(p));
    return a;
}
__device__ __forceinline__ void cp_async16(uint32_t dst, const void* src) {
    asm volatile("cp.async.cg.shared.global [%0], [%1], 16;" :: "r"(dst), "l"(src));
}
__device__ __forceinline__ void cp_commit() {
    asm volatile("cp.async.commit_group;" ::: "memory");
}
template <int N> __device__ __forceinline__ void cp_wait() {
    asm volatile("cp.async.wait_group %0;" :: "n"(N) : "memory");
}
__device__ __forceinline__ void ldsm4(uint32_t* r, uint32_t addr) {
    asm volatile("ldmatrix.sync.aligned.m8n8.x4.shared.b16 {%0,%1,%2,%3}, [%4];"
        : "=r"(r[0]), "=r"(r[1]), "=r"(r[2]), "=r"(r[3]) : "r"(addr));
}
__device__ __forceinline__ void ldsm4t(uint32_t* r, uint32_t addr) {
    asm volatile("ldmatrix.sync.aligned.m8n8.x4.trans.shared.b16 {%0,%1,%2,%3}, [%4];"
        : "=r"(r[0]), "=r"(r[1]), "=r"(r[2]), "=r"(r[3]) : "r"(addr));
}
__device__ __forceinline__ void mma_f16(float* c, const uint32_t* a, uint32_t b0, uint32_t b1) {
    asm volatile(
        "mma.sync.aligned.m16n8k16.row.col.f32.f16.f16.f32 "
        "{%0,%1,%2,%3}, {%4,%5,%6,%7}, {%8,%9}, {%0,%1,%2,%3};"
        : "+f"(c[0]), "+f"(c[1]), "+f"(c[2]), "+f"(c[3])
        : "r"(a[0]), "r"(a[1]), "r"(a[2]), "r"(a[3]), "r"(b0), "r"(b1));
}

// ---------------------------------------------------------------------------
// Merged conversion: x, W1, W2 -> fp16 in ONE launch (range dispatch).
// ---------------------------------------------------------------------------
#define XN4  (MROWS * KDIM / 4)          // 1048576
#define W1N4 (E3 * KDIM / 4)             // 786432
#define W2N4 (EMB * KDIM / 4)            // 262144
#define ALLN4 (XN4 + W1N4 + W2N4)        // 2097152

__global__ void convert_all(const float* __restrict__ x, const float* __restrict__ W1,
                            const float* __restrict__ W2,
                            __half* __restrict__ x16, __half* __restrict__ w1,
                            __half* __restrict__ w2)
{
    int i = blockIdx.x * blockDim.x + threadIdx.x;
    const float* src;
    __half* dst;
    int j;
    if (i < XN4) {
        src = x; dst = x16; j = i;
    } else if (i < XN4 + W1N4) {
        src = W1; dst = w1; j = i - XN4;
    } else if (i < ALLN4) {
        src = W2; dst = w2; j = i - XN4 - W1N4;
    } else {
        return;
    }
    float4 v = ((const float4*)src)[j];
    __half2* dp = (__half2*)dst;
    dp[2 * j]     = __floats2half2_rn(v.x, v.y);
    dp[2 * j + 1] = __floats2half2_rn(v.z, v.w);
}

// ---------------------------------------------------------------------------
// fp16 mma GEMM, persistent tiles. C[M,N] = A[M,K] @ B[N,K]^T.
// MODE 0: fp32 C out.  MODE 2: fused RoPE+repack epilogue to qh/kh/vh.
// 128x128x64 tiles, 256 threads (8 warps 4m x 2n), 3-stage cp.async ring.
// Inner loop: ALL fragment ldsm hoisted before the MMA burst per ks-step.
// ---------------------------------------------------------------------------
#define GBM 128
#define GBN 128
#define GBK 64
#define GSK 72                        // padded smem stride (halves)
#define GMAT (GBM * GSK)              // 9216 halves per matrix tile
#define GSTAGE (2 * GMAT * 2)         // A,B per stage = 36864 bytes
#define GEMM_SMEM (3 * GSTAGE)        // 110592 bytes
#define NCH (KDIM / GBK)              // 16

__device__ __forceinline__ void g2_load(
    uint32_t s0, int tid, int kc, int m0, int n0,
    const __half* __restrict__ A, const __half* __restrict__ B)
{
    const __half* a0 = A + (size_t)m0 * KDIM + kc * GBK;
    const __half* b0 = B + (size_t)n0 * KDIM + kc * GBK;
    #pragma unroll
    for (int it = 0; it < 4; it++) {
        const int jj = tid + it * 256;      // 0..1023
        const int row = jj >> 3;
        const int c = jj & 7;
        const uint32_t d = s0 + (uint32_t)(row * GSK + c * 8) * 2;
        const size_t goff = (size_t)row * KDIM + c * 8;
        cp_async16(d, a0 + goff);
        cp_async16(d + GMAT * 2, b0 + goff);
    }
    cp_commit();
}

template <int MODE>
__global__ void __launch_bounds__(256, 2)
gemm_f16(const __half* __restrict__ A, const __half* __restrict__ B,
         float* __restrict__ C, int N, int numTiles,
         __half* __restrict__ qh, __half* __restrict__ kh, __half* __restrict__ vh)
{
    extern __shared__ char smem[];
    const uint32_t sb = smem_u32(smem);
    const int tid = threadIdx.x;
    const int wid = tid >> 5;
    const int lane = tid & 31;
    const int wm = wid >> 1;    // 0..3
    const int wn = wid & 1;     // 0..1
    const int ntiles_n = N / GBN;

    float invf[8];
    if (MODE == 2) {
        #pragma unroll
        for (int p = 0; p < 4; p++) {
            const int j0 = p * 8 + 2 * (lane & 3);
            invf[2 * p]     = exp2f(-(float)j0 * LOG2_10000_OVER32);
            invf[2 * p + 1] = exp2f(-(float)(j0 + 1) * LOG2_10000_OVER32);
        }
    }

    for (int t = blockIdx.x; t < numTiles; t += gridDim.x) {
        const int m0 = (t / ntiles_n) * GBM;
        const int n0 = (t % ntiles_n) * GBN;

        float acc[2][8][4];
        #pragma unroll
        for (int i = 0; i < 2; i++)
            #pragma unroll
            for (int j = 0; j < 8; j++)
                #pragma unroll
                for (int k = 0; k < 4; k++) acc[i][j][k] = 0.f;

        g2_load(sb,          tid, 0, m0, n0, A, B);
        g2_load(sb + GSTAGE, tid, 1, m0, n0, A, B);

        for (int c = 0; c < NCH; c++) {
            if (c + 1 < NCH) cp_wait<1>(); else cp_wait<0>();
            __syncthreads();

            const uint32_t scur = sb + (uint32_t)(c % 3) * GSTAGE;
            const uint32_t sA = scur;
            const uint32_t sB = scur + GMAT * 2;

            #pragma unroll
            for (int ks = 0; ks < 4; ks++) {
                const int k0 = ks * 16;
                // hoist ALL fragment loads for this ks-step
                uint32_t aF[2][4], bk[4][4];
                #pragma unroll
                for (int mi = 0; mi < 2; mi++) {
                    const int row = wm * 32 + mi * 16 + (lane & 15);
                    const int col = k0 + ((lane >> 4) << 3);
                    ldsm4(aF[mi], sA + (uint32_t)(row * GSK + col) * 2);
                }
                #pragma unroll
                for (int p = 0; p < 4; p++) {
                    const int row = wn * 64 + p * 16 + (lane & 7) + ((lane >> 4) << 3);
                    const int col = k0 + (((lane >> 3) & 1) << 3);
                    ldsm4(bk[p], sB + (uint32_t)(row * GSK + col) * 2);
                }
                // MMA burst (16 independent-target MMAs)
                #pragma unroll
                for (int p = 0; p < 4; p++) {
                    #pragma unroll
                    for (int mi = 0; mi < 2; mi++) {
                        mma_f16(acc[mi][2 * p],     aF[mi], bk[p][0], bk[p][1]);
                        mma_f16(acc[mi][2 * p + 1], aF[mi], bk[p][2], bk[p][3]);
                    }
                }
            }
            if (c + 2 < NCH)
                g2_load(sb + (uint32_t)((c + 2) % 3) * GSTAGE, tid, c + 2, m0, n0, A, B);
        }

        if (MODE == 0) {
            #pragma unroll
            for (int mi = 0; mi < 2; mi++) {
                const int r0 = m0 + wm * 32 + mi * 16 + (lane >> 2);
                #pragma unroll
                for (int nj = 0; nj < 8; nj++) {
                    const int col = n0 + wn * 64 + nj * 8 + 2 * (lane & 3);
                    *(float2*)&C[(size_t)r0 * N + col] =
                        make_float2(acc[mi][nj][0], acc[mi][nj][1]);
                    *(float2*)&C[(size_t)(r0 + 8) * N + col] =
                        make_float2(acc[mi][nj][2], acc[mi][nj][3]);
                }
            }
        } else {
            // fused RoPE + repack epilogue (warp owns one head of q/k/v)
            const int cbase = n0 + wn * 64;
            const int sec = cbase >> 10;            // 0=q 1=k 2=v
            const int hd  = (cbase & 1023) >> 6;
            __half* dst = (sec == 0) ? qh : (sec == 1) ? kh : vh;

            #pragma unroll
            for (int mi = 0; mi < 2; mi++) {
                #pragma unroll
                for (int rr = 0; rr < 2; rr++) {
                    const int r = m0 + wm * 32 + mi * 16 + (lane >> 2) + rr * 8;
                    const int bb = r >> 11;
                    const int tt = r & 2047;
                    __half* drow = dst + ((size_t)((bb * NHEAD + hd) * SEQT + tt)) * HDIM;
                    if (sec == 2) {
                        #pragma unroll
                        for (int nj = 0; nj < 8; nj++) {
                            const int j0 = nj * 8 + 2 * (lane & 3);
                            *(__half2*)&drow[j0] =
                                __floats2half2_rn(acc[mi][nj][2 * rr], acc[mi][nj][2 * rr + 1]);
                        }
                    } else {
                        const float qs = (sec == 0) ? QSCALE : 1.0f;
                        const float tf = (float)tt;
                        #pragma unroll
                        for (int p = 0; p < 4; p++) {
                            const int j0 = p * 8 + 2 * (lane & 3);
                            const float a0 = acc[mi][p][2 * rr];
                            const float a1 = acc[mi][p][2 * rr + 1];
                            const float b0 = acc[mi][p + 4][2 * rr];
                            const float b1 = acc[mi][p + 4][2 * rr + 1];
                            float s0, c0, s1, c1;
                            sincosf(tf * invf[2 * p], &s0, &c0);
                            sincosf(tf * invf[2 * p + 1], &s1, &c1);
                            *(__half2*)&drow[j0] =
                                __floats2half2_rn(qs * (a0 * c0 - b0 * s0),
                                                  qs * (a1 * c1 - b1 * s1));
                            *(__half2*)&drow[j0 + 32] =
                                __floats2half2_rn(qs * (b0 * c0 + a0 * s0),
                                                  qs * (b1 * c1 + a1 * s1));
                        }
                    }
                }
            }
        }
        __syncthreads();
    }
}

// ---------------------------------------------------------------------------
// fp16 mma causal flash attention. 256 threads (8 warps), 128 queries per
// block. K-tile = 64, double-buffered cp.async. exp2-domain softmax.
// Fully-masked warp tiles skip compute. Dynamic smem 55296 B.
// ---------------------------------------------------------------------------
#define SV 72   // smem row stride (halves)
#define AQT 128
#define ATTN_SQ_OFF 0
#define ATTN_SK_OFF (AQT * SV * 2)                    // 18432
#define ATTN_SV_OFF (ATTN_SK_OFF + 2 * 64 * SV * 2)   // 36864
#define ATTN_SMEM   (ATTN_SV_OFF + 2 * 64 * SV * 2)   // 55296

__global__ void __launch_bounds__(256, 2) attn_mma(
    const __half* __restrict__ qh, const __half* __restrict__ kh,
    const __half* __restrict__ vh, __half* __restrict__ outh)
{
    extern __shared__ char asmem[];
    const uint32_t sbase = smem_u32(asmem);
    const uint32_t sQ = sbase + ATTN_SQ_OFF;
    const uint32_t sKb[2] = { sbase + ATTN_SK_OFF, sbase + ATTN_SK_OFF + 64 * SV * 2 };
    const uint32_t sVb[2] = { sbase + ATTN_SV_OFF, sbase + ATTN_SV_OFF + 64 * SV * 2 };

    const int bh = blockIdx.y;
    const int b = bh >> 4;
    const int h = bh & 15;
    const int qt = (gridDim.x - 1) - blockIdx.x;   // heavy tiles first
    const int tid = threadIdx.x;
    const int wid = tid >> 5;
    const int lane = tid & 31;

    const __half* qg = qh + (size_t)bh * SEQT * HDIM;
    const __half* kg = kh + (size_t)bh * SEQT * HDIM;
    const __half* vg = vh + (size_t)bh * SEQT * HDIM;

    #pragma unroll
    for (int i = 0; i < 4; i++) {
        const int ch = tid + i * 256;
        const int row = ch >> 3;
        const int c = ch & 7;
        cp_async16(sQ + (uint32_t)(row * SV + c * 8) * 2,
                   qg + (size_t)(qt * AQT + row) * HDIM + c * 8);
    }
    cp_commit();

    {
        #pragma unroll
        for (int i = 0; i < 2; i++) {
            const int ch = tid + i * 256;
            const int row = ch >> 3;
            const int c = ch & 7;
            const uint32_t d = (uint32_t)(row * SV + c * 8) * 2;
            const size_t goff = (size_t)row * HDIM + c * 8;
            cp_async16(sKb[0] + d, kg + goff);
            cp_async16(sVb[0] + d, vg + goff);
        }
        cp_commit();
    }

    cp_wait<1>();
    __syncthreads();

    uint32_t aq[4][4];
    #pragma unroll
    for (int ks = 0; ks < 4; ks++) {
        const int row = wid * 16 + (lane & 15);
        const int col = ks * 16 + ((lane >> 4) << 3);
        ldsm4(aq[ks], sQ + (uint32_t)(row * SV + col) * 2);
    }

    float o[8][4];
    #pragma unroll
    for (int j = 0; j < 8; j++)
        #pragma unroll
        for (int k = 0; k < 4; k++) o[j][k] = 0.f;
    float mr[2] = {-1e30f, -1e30f};
    float lr[2] = {0.f, 0.f};

    const int q0g = qt * AQT + wid * 16;
    const int NKT = 2 * qt + 2;

    for (int kt = 0; kt < NKT; kt++) {
        const int cb = kt & 1;
        if (kt + 1 < NKT) {
            const uint32_t sKn = sKb[1 - cb];
            const uint32_t sVn = sVb[1 - cb];
            #pragma unroll
            for (int i = 0; i < 2; i++) {
                const int ch = tid + i * 256;
                const int row = ch >> 3;
                const int c = ch & 7;
                const uint32_t d = (uint32_t)(row * SV + c * 8) * 2;
                const size_t goff = (size_t)((kt + 1) * 64 + row) * HDIM + c * 8;
                cp_async16(sKn + d, kg + goff);
                cp_async16(sVn + d, vg + goff);
            }
            cp_commit();
            cp_wait<1>();
        } else {
            cp_wait<0>();
        }
        __syncthreads();

        const int kbase = kt * 64;
        const bool active = (kbase <= q0g + 15);
        if (active) {
            const uint32_t sK = sKb[cb];
            const uint32_t sV = sVb[cb];

            float sacc[8][4];
            #pragma unroll
            for (int j = 0; j < 8; j++)
                #pragma unroll
                for (int k = 0; k < 4; k++) sacc[j][k] = 0.f;

            #pragma unroll
            for (int ks = 0; ks < 4; ks++) {
                uint32_t bk[4][4];
                #pragma unroll
                for (int p = 0; p < 4; p++) {
                    const int row = p * 16 + (lane & 7) + ((lane >> 4) << 3);
                    const int col = ks * 16 + (((lane >> 3) & 1) << 3);
                    ldsm4(bk[p], sK + (uint32_t)(row * SV + col) * 2);
                }
                #pragma unroll
                for (int p = 0; p < 4; p++) {
                    mma_f16(sacc[2 * p],     aq[ks], bk[p][0], bk[p][1]);
                    mma_f16(sacc[2 * p + 1], aq[ks], bk[p][2], bk[p][3]);
                }
            }

            if (kbase + 63 > q0g) {
                const int qg0 = q0g + (lane >> 2);
                #pragma unroll
                for (int nj = 0; nj < 8; nj++) {
                    const int col = kbase + nj * 8 + 2 * (lane & 3);
                    if (col > qg0)         sacc[nj][0] = -1e30f;
                    if (col + 1 > qg0)     sacc[nj][1] = -1e30f;
                    if (col > qg0 + 8)     sacc[nj][2] = -1e30f;
                    if (col + 1 > qg0 + 8) sacc[nj][3] = -1e30f;
                }
            }

            #pragma unroll
            for (int r = 0; r < 2; r++) {
                float mt = -1e30f;
                #pragma unroll
                for (int nj = 0; nj < 8; nj++)
                    mt = fmaxf(mt, fmaxf(sacc[nj][2 * r], sacc[nj][2 * r + 1]));
                mt = fmaxf(mt, __shfl_xor_sync(0xFFFFFFFFu, mt, 1));
                mt = fmaxf(mt, __shfl_xor_sync(0xFFFFFFFFu, mt, 2));
                const float mnew = fmaxf(mr[r], mt);
                const float alpha = exp2f(mr[r] - mnew);
                mr[r] = mnew;
                lr[r] *= alpha;
                #pragma unroll
                for (int nj = 0; nj < 8; nj++) {
                    o[nj][2 * r] *= alpha;
                    o[nj][2 * r + 1] *= alpha;
                }
                float psum = 0.f;
                #pragma unroll
                for (int nj = 0; nj < 8; nj++) {
                    const float p0 = exp2f(sacc[nj][2 * r] - mnew);
                    const float p1 = exp2f(sacc[nj][2 * r + 1] - mnew);
                    sacc[nj][2 * r] = p0;
                    sacc[nj][2 * r + 1] = p1;
                    psum += p0 + p1;
                }
                lr[r] += psum;
            }

            uint32_t ap[4][4];
            #pragma unroll
            for (int kp = 0; kp < 4; kp++) {
                const int nj = 2 * kp;
                __half2 t0 = __float22half2_rn(make_float2(sacc[nj][0], sacc[nj][1]));
                __half2 t1 = __float22half2_rn(make_float2(sacc[nj][2], sacc[nj][3]));
                __half2 t2 = __float22half2_rn(make_float2(sacc[nj + 1][0], sacc[nj + 1][1]));
                __half2 t3 = __float22half2_rn(make_float2(sacc[nj + 1][2], sacc[nj + 1][3]));
                ap[kp][0] = *(uint32_t*)&t0;
                ap[kp][1] = *(uint32_t*)&t1;
                ap[kp][2] = *(uint32_t*)&t2;
                ap[kp][3] = *(uint32_t*)&t3;
            }

            #pragma unroll
            for (int kp = 0; kp < 4; kp++) {
                uint32_t bv[4][4];
                #pragma unroll
                for (int pd = 0; pd < 4; pd++) {
                    const int row = kp * 16 + (lane & 7) + ((lane >> 4) << 3);
                    const int col = pd * 16 + (((lane >> 3) & 1) << 3);
                    ldsm4t(bv[pd], sV + (uint32_t)(row * SV + col) * 2);
                }
                #pragma unroll
                for (int pd = 0; pd < 4; pd++) {
                    mma_f16(o[2 * pd],     ap[kp], bv[pd][0], bv[pd][2]);
                    mma_f16(o[2 * pd + 1], ap[kp], bv[pd][1], bv[pd][3]);
                }
            }
        }
        __syncthreads();
    }

    float inv[2];
    #pragma unroll
    for (int r = 0; r < 2; r++) {
        float ls = lr[r];
        ls += __shfl_xor_sync(0xFFFFFFFFu, ls, 1);
        ls += __shfl_xor_sync(0xFFFFFFFFu, ls, 2);
        inv[r] = 1.0f / ls;
    }
    #pragma unroll
    for (int r = 0; r < 2; r++) {
        const int trow = qt * AQT + wid * 16 + (lane >> 2) + 8 * r;
        const size_t rowoff = (size_t)(b * SEQT + trow) * EMB + h * HDIM;
        #pragma unroll
        for (int nj = 0; nj < 8; nj++) {
            const int col = nj * 8 + 2 * (lane & 3);
            *(__half2*)&outh[rowoff + col] =
                __floats2half2_rn(o[nj][2 * r] * inv[r], o[nj][2 * r + 1] * inv[r]);
        }
    }
}

// ---------------------------------------------------------------------------
// Launch sequence
// ---------------------------------------------------------------------------
extern "C" void kernel_launch(void* const* d_in, const int* in_sizes, int n_in,
                              void* d_out, int out_size)
{
    const float* x  = (const float*)d_in[0];
    const float* W1 = (const float*)d_in[1];
    const float* W2 = (const float*)d_in[2];
    float* out = (float*)d_out;

    void *p_x16, *p_w1, *p_w2, *p_ah, *p_qh, *p_kh, *p_vh;
    cudaGetSymbolAddress(&p_x16, g_x16);
    cudaGetSymbolAddress(&p_w1, g_w1); cudaGetSymbolAddress(&p_w2, g_w2);
    cudaGetSymbolAddress(&p_ah, g_ah);
    cudaGetSymbolAddress(&p_qh, g_qh); cudaGetSymbolAddress(&p_kh, g_kh);
    cudaGetSymbolAddress(&p_vh, g_vh);

    cudaFuncSetAttribute(gemm_f16<0>, cudaFuncAttributeMaxDynamicSharedMemorySize, GEMM_SMEM);
    cudaFuncSetAttribute(gemm_f16<2>, cudaFuncAttributeMaxDynamicSharedMemorySize, GEMM_SMEM);
    cudaFuncSetAttribute(attn_mma,    cudaFuncAttributeMaxDynamicSharedMemorySize, ATTN_SMEM);

    // one merged conversion launch
    convert_all<<<(ALLN4 + 255) / 256, 256>>>(
        x, W1, W2, (__half*)p_x16, (__half*)p_w1, (__half*)p_w2);

    // qkv = x @ W1^T with fused RoPE + repack epilogue (persistent tiles)
    {
        const int tiles = (MROWS / GBM) * (E3 / GBN);   // 768
        const int grid = tiles < PGRID ? tiles : PGRID;
        gemm_f16<2><<<grid, 256, GEMM_SMEM>>>(
            (const __half*)p_x16, (const __half*)p_w1, nullptr, E3, tiles,
            (__half*)p_qh, (__half*)p_kh, (__half*)p_vh);
    }

    // attention -> fp16
    {
        dim3 ga(SEQT / AQT, BATCH * NHEAD);
        attn_mma<<<ga, 256, ATTN_SMEM>>>((const __half*)p_qh, (const __half*)p_kh,
                                         (const __half*)p_vh, (__half*)p_ah);
    }

    // out = att @ W2^T  (fp32 out, single pass, persistent tiles)
    {
        const int tiles = (MROWS / GBM) * (EMB / GBN);  // 256
        const int grid = tiles < PGRID ? tiles : PGRID;
        gemm_f16<0><<<grid, 256, GEMM_SMEM>>>(
            (const __half*)p_ah, (const __half*)p_w2, out, EMB, tiles,
            nullptr, nullptr, nullptr);
    }
}